// round 10
// baseline (speedup 1.0000x reference)
#include <cuda_runtime.h>
#include <cuda_bf16.h>
#include <cstdint>

#define NMAX 50000
#define EMAX 600000
#define HID 128
#define INDIM 256
#define BN_EPS 1e-5f
#define SCAN_BLK 256

// ---------------- scratch (no allocations allowed) ----------------
__device__ float g_h[(size_t)NMAX * HID];         // x @ W
__device__ __nv_bfloat16 g_wt_hi[HID * INDIM];    // W^T split hi: [n][k]
__device__ __nv_bfloat16 g_wt_lo[HID * INDIM];    // W^T split lo: [n][k]
__device__ int   g_degE[NMAX];
__device__ int   g_scan[NMAX];
__device__ int   g_rowptr[NMAX];
__device__ int   g_cursor[NMAX];
__device__ int   g_bsum[SCAN_BLK];
__device__ int   g_csr_src[EMAX];
__device__ float g_dinv[NMAX];
__device__ float g_sum[HID];
__device__ float g_sumsq[HID];

// ---------------- K0a (side stream): zero edge state ----------------
__global__ void k_initE(int N) {
    int i = blockIdx.x * blockDim.x + threadIdx.x;
    if (i < N) { g_degE[i] = 0; g_cursor[i] = 0; }
    if (i < SCAN_BLK) g_bsum[i] = 0;
}

// ---------------- K0b (main stream): zero BN stats ----------------
__global__ void k_initS() {
    g_sum[threadIdx.x] = 0.0f;
    g_sumsq[threadIdx.x] = 0.0f;
}

// ---------------- Kw: transpose + bf16-split W -> g_wt_hi/lo [n][k] ----------------
__global__ void k_wsplit(const float* __restrict__ W) {
    int n = blockIdx.x;
    for (int k = threadIdx.x; k < INDIM; k += blockDim.x) {
        float f = W[(size_t)k * HID + n];
        __nv_bfloat16 h = __float2bfloat16(f);
        float r = f - __bfloat162float(h);
        g_wt_hi[n * INDIM + k] = h;
        g_wt_lo[n * INDIM + k] = __float2bfloat16(r);
    }
}

// ================= K1: HMMA GEMM  h = x @ W  via bf16-split, double-buffered =================
#define PITCH 72
#define PLANE (128 * PITCH * 2)          // bytes per plane = 18432
#define BUFSZ (4 * PLANE)                // one buffer = 4 planes = 73728
#define SA_HI 0
#define SA_LO (PLANE)
#define SB_HI (2 * PLANE)
#define SB_LO (3 * PLANE)
#define SM_GEMM (2 * BUFSZ)              // 147456 B (double buffer)

__device__ __forceinline__ void mma16816(float c[4], uint32_t a0, uint32_t a1,
                                         uint32_t a2, uint32_t a3,
                                         uint32_t b0, uint32_t b1) {
    asm volatile("mma.sync.aligned.m16n8k16.row.col.f32.bf16.bf16.f32 "
                 "{%0,%1,%2,%3},{%4,%5,%6,%7},{%8,%9},{%0,%1,%2,%3};"
                 : "+f"(c[0]), "+f"(c[1]), "+f"(c[2]), "+f"(c[3])
                 : "r"(a0), "r"(a1), "r"(a2), "r"(a3), "r"(b0), "r"(b1));
}

__global__ __launch_bounds__(256, 1)
void k_gemm_mma(const float* __restrict__ x, int M) {
    extern __shared__ char smem[];
    const int tid  = threadIdx.x;
    const int wid  = tid >> 5;
    const int lane = tid & 31;
    const int m0   = blockIdx.x * 128;

    const int wm = wid & 3;
    const int wn = wid >> 2;

    float c[2][8][4];
    #pragma unroll
    for (int mf = 0; mf < 2; mf++)
        #pragma unroll
        for (int nf = 0; nf < 8; nf++)
            #pragma unroll
            for (int q = 0; q < 4; q++) c[mf][nf][q] = 0.0f;

    const int srow = tid >> 1;
    const int half = tid & 1;
    const bool arow_ok = (m0 + srow) < M;

    const int groupID = lane >> 2;
    const int tq      = lane & 3;

    const float4* xsrc  = (const float4*)(x + (size_t)(m0 + srow) * INDIM + half * 32);
    const uint4*  whsrc = (const uint4*)(g_wt_hi + (size_t)srow * INDIM + half * 32);
    const uint4*  wlsrc = (const uint4*)(g_wt_lo + (size_t)srow * INDIM + half * 32);

    float4 fx[8];
    uint4  bh[4], bl[4];

    #pragma unroll
    for (int v = 0; v < 8; v++)
        fx[v] = arow_ok ? xsrc[v] : make_float4(0.f, 0.f, 0.f, 0.f);
    #pragma unroll
    for (int v = 0; v < 4; v++) { bh[v] = whsrc[v]; bl[v] = wlsrc[v]; }

    #pragma unroll 1
    for (int ch = 0; ch < INDIM / 64; ch++) {
        char* base = smem + (ch & 1) * BUFSZ;
        {
            char* ahi = base + SA_HI + (size_t)srow * PITCH * 2 + half * 64;
            char* alo = base + SA_LO + (size_t)srow * PITCH * 2 + half * 64;
            #pragma unroll
            for (int v = 0; v < 8; v++) {
                float4 f = fx[v];
                __nv_bfloat16 hx = __float2bfloat16(f.x), hy = __float2bfloat16(f.y);
                __nv_bfloat16 hz = __float2bfloat16(f.z), hw = __float2bfloat16(f.w);
                __nv_bfloat162 h01 = {hx, hy}, h23 = {hz, hw};
                __nv_bfloat162 l01 = {__float2bfloat16(f.x - __bfloat162float(hx)),
                                      __float2bfloat16(f.y - __bfloat162float(hy))};
                __nv_bfloat162 l23 = {__float2bfloat16(f.z - __bfloat162float(hz)),
                                      __float2bfloat16(f.w - __bfloat162float(hw))};
                *(uint32_t*)(ahi + v * 8)     = *(uint32_t*)&h01;
                *(uint32_t*)(ahi + v * 8 + 4) = *(uint32_t*)&h23;
                *(uint32_t*)(alo + v * 8)     = *(uint32_t*)&l01;
                *(uint32_t*)(alo + v * 8 + 4) = *(uint32_t*)&l23;
            }
            char* bhi = base + SB_HI + (size_t)srow * PITCH * 2 + half * 64;
            char* blo = base + SB_LO + (size_t)srow * PITCH * 2 + half * 64;
            #pragma unroll
            for (int v = 0; v < 4; v++) {
                *(uint4*)(bhi + v * 16) = bh[v];
                *(uint4*)(blo + v * 16) = bl[v];
            }
        }
        __syncthreads();   // single sync per chunk: separates stores(ch) from MMA(ch)
                           // and (via prior iteration) MMA(ch-2) reads from stores(ch)

        if (ch < INDIM / 64 - 1) {
            #pragma unroll
            for (int v = 0; v < 8; v++)
                fx[v] = arow_ok ? xsrc[(ch + 1) * 16 + v] : make_float4(0.f, 0.f, 0.f, 0.f);
            #pragma unroll
            for (int v = 0; v < 4; v++) {
                bh[v] = whsrc[(ch + 1) * 8 + v];
                bl[v] = wlsrc[(ch + 1) * 8 + v];
            }
        }

        #pragma unroll
        for (int ks = 0; ks < 4; ks++) {
            const int kk = ks * 16 + 2 * tq;
            uint32_t ahi[2][4], alo[2][4];
            #pragma unroll
            for (int mf = 0; mf < 2; mf++) {
                int r0 = wm * 32 + mf * 16 + groupID;
                const char* ph = base + SA_HI;
                const char* pl = base + SA_LO;
                ahi[mf][0] = *(const uint32_t*)(ph + ((size_t)r0 * PITCH + kk) * 2);
                ahi[mf][1] = *(const uint32_t*)(ph + ((size_t)(r0 + 8) * PITCH + kk) * 2);
                ahi[mf][2] = *(const uint32_t*)(ph + ((size_t)r0 * PITCH + kk + 8) * 2);
                ahi[mf][3] = *(const uint32_t*)(ph + ((size_t)(r0 + 8) * PITCH + kk + 8) * 2);
                alo[mf][0] = *(const uint32_t*)(pl + ((size_t)r0 * PITCH + kk) * 2);
                alo[mf][1] = *(const uint32_t*)(pl + ((size_t)(r0 + 8) * PITCH + kk) * 2);
                alo[mf][2] = *(const uint32_t*)(pl + ((size_t)r0 * PITCH + kk + 8) * 2);
                alo[mf][3] = *(const uint32_t*)(pl + ((size_t)(r0 + 8) * PITCH + kk + 8) * 2);
            }
            #pragma unroll
            for (int nf = 0; nf < 8; nf++) {
                int nr = wn * 64 + nf * 8 + groupID;
                uint32_t bh0 = *(const uint32_t*)(base + SB_HI + ((size_t)nr * PITCH + kk) * 2);
                uint32_t bh1 = *(const uint32_t*)(base + SB_HI + ((size_t)nr * PITCH + kk + 8) * 2);
                uint32_t bl0 = *(const uint32_t*)(base + SB_LO + ((size_t)nr * PITCH + kk) * 2);
                uint32_t bl1 = *(const uint32_t*)(base + SB_LO + ((size_t)nr * PITCH + kk + 8) * 2);
                #pragma unroll
                for (int mf = 0; mf < 2; mf++) {
                    mma16816(c[mf][nf], ahi[mf][0], ahi[mf][1], ahi[mf][2], ahi[mf][3], bh0, bh1);
                    mma16816(c[mf][nf], ahi[mf][0], ahi[mf][1], ahi[mf][2], ahi[mf][3], bl0, bl1);
                    mma16816(c[mf][nf], alo[mf][0], alo[mf][1], alo[mf][2], alo[mf][3], bh0, bh1);
                }
            }
        }
    }

    #pragma unroll
    for (int mf = 0; mf < 2; mf++) {
        int r0 = m0 + wm * 32 + mf * 16 + groupID;
        #pragma unroll
        for (int nf = 0; nf < 8; nf++) {
            int n0 = wn * 64 + nf * 8 + 2 * tq;
            if (r0 < M)
                *(float2*)(g_h + (size_t)r0 * HID + n0) = make_float2(c[mf][nf][0], c[mf][nf][1]);
            if (r0 + 8 < M)
                *(float2*)(g_h + (size_t)(r0 + 8) * HID + n0) = make_float2(c[mf][nf][2], c[mf][nf][3]);
        }
    }
}

// ---------------- K2: in-degree on targets (4 edges/thread, int4) ----------------
__global__ void k_deg(const int* __restrict__ ei, int E) {
    int t = blockIdx.x * blockDim.x + threadIdx.x;
    int e4 = t * 4;
    if (e4 + 3 < E) {
        int4 cc = *(const int4*)(ei + E + e4);
        atomicAdd(&g_degE[cc.x], 1);
        atomicAdd(&g_degE[cc.y], 1);
        atomicAdd(&g_degE[cc.z], 1);
        atomicAdd(&g_degE[cc.w], 1);
    } else {
        for (int e = e4; e < E; e++) atomicAdd(&g_degE[ei[E + e]], 1);
    }
}

// ---------------- warp-shuffle inclusive scan helpers ----------------
__device__ __forceinline__ int warp_iscan(int v, int lane) {
    #pragma unroll
    for (int off = 1; off < 32; off <<= 1) {
        int t = __shfl_up_sync(0xFFFFFFFF, v, off);
        if (lane >= off) v += t;
    }
    return v;
}

__global__ void k_scan1(int N) {
    __shared__ int wsum[8];
    int i = blockIdx.x * SCAN_BLK + threadIdx.x;
    int lane = threadIdx.x & 31, wid = threadIdx.x >> 5;
    int v = (i < N) ? g_degE[i] : 0;
    v = warp_iscan(v, lane);
    if (lane == 31) wsum[wid] = v;
    __syncthreads();
    if (wid == 0) {
        int s = (lane < 8) ? wsum[lane] : 0;
        s = warp_iscan(s, lane);
        if (lane < 8) wsum[lane] = s;
    }
    __syncthreads();
    if (wid > 0) v += wsum[wid - 1];
    if (i < N) g_scan[i] = v;
    if (threadIdx.x == SCAN_BLK - 1) g_bsum[blockIdx.x] = v;
}

__global__ void k_scan2(int nblk) {
    __shared__ int wsum[8];
    int lane = threadIdx.x & 31, wid = threadIdx.x >> 5;
    int v = (threadIdx.x < nblk) ? g_bsum[threadIdx.x] : 0;
    v = warp_iscan(v, lane);
    if (lane == 31) wsum[wid] = v;
    __syncthreads();
    if (wid == 0) {
        int s = (lane < 8) ? wsum[lane] : 0;
        s = warp_iscan(s, lane);
        if (lane < 8) wsum[lane] = s;
    }
    __syncthreads();
    if (wid > 0) v += wsum[wid - 1];
    g_bsum[threadIdx.x] = v;
}

__global__ void k_scan3(int N) {
    int i = blockIdx.x * SCAN_BLK + threadIdx.x;
    if (i >= N) return;
    int base = (blockIdx.x > 0) ? g_bsum[blockIdx.x - 1] : 0;
    g_rowptr[i] = base + g_scan[i] - g_degE[i];
    g_dinv[i]   = rsqrtf((float)(g_degE[i] + 1));
}

// ---------------- K4: fill CSR source list (4 edges/thread) ----------------
__global__ void k_fill(const int* __restrict__ ei, int E) {
    int t = blockIdx.x * blockDim.x + threadIdx.x;
    int e4 = t * 4;
    if (e4 + 3 < E) {
        int4 rr = *(const int4*)(ei + e4);
        int4 cc = *(const int4*)(ei + E + e4);
        int p;
        p = atomicAdd(&g_cursor[cc.x], 1); g_csr_src[g_rowptr[cc.x] + p] = rr.x;
        p = atomicAdd(&g_cursor[cc.y], 1); g_csr_src[g_rowptr[cc.y] + p] = rr.y;
        p = atomicAdd(&g_cursor[cc.z], 1); g_csr_src[g_rowptr[cc.z] + p] = rr.z;
        p = atomicAdd(&g_cursor[cc.w], 1); g_csr_src[g_rowptr[cc.w] + p] = rr.w;
    } else {
        for (int e = e4; e < E; e++) {
            int r = ei[e], c = ei[E + e];
            int p = atomicAdd(&g_cursor[c], 1);
            g_csr_src[g_rowptr[c] + p] = r;
        }
    }
}

// ---------------- K5: gather-reduce + fused BN stats (2-way unrolled) ----------------
__global__ void k_gather(float* __restrict__ out, int N) {
    __shared__ float sh[8][HID];
    __shared__ float sh2[8][HID];
    const int wid  = threadIdx.x >> 5;
    const int lane = threadIdx.x & 31;
    const int node = blockIdx.x * 8 + wid;

    float4 acc = make_float4(0.f, 0.f, 0.f, 0.f);
    if (node < N) {
        float di = g_dinv[node];
        acc = ((const float4*)(g_h + (size_t)node * HID))[lane];
        float n2 = di * di;
        acc.x *= n2; acc.y *= n2; acc.z *= n2; acc.w *= n2;

        int s  = g_rowptr[node];
        int e2 = s + g_degE[node];
        float4 acc2 = make_float4(0.f, 0.f, 0.f, 0.f);
        int j = s;
        for (; j + 1 < e2; j += 2) {
            int r0 = g_csr_src[j];
            int r1 = g_csr_src[j + 1];
            float nr0 = di * g_dinv[r0];
            float nr1 = di * g_dinv[r1];
            float4 v0 = ((const float4*)(g_h + (size_t)r0 * HID))[lane];
            float4 v1 = ((const float4*)(g_h + (size_t)r1 * HID))[lane];
            acc.x  = fmaf(v0.x, nr0, acc.x);
            acc.y  = fmaf(v0.y, nr0, acc.y);
            acc.z  = fmaf(v0.z, nr0, acc.z);
            acc.w  = fmaf(v0.w, nr0, acc.w);
            acc2.x = fmaf(v1.x, nr1, acc2.x);
            acc2.y = fmaf(v1.y, nr1, acc2.y);
            acc2.z = fmaf(v1.z, nr1, acc2.z);
            acc2.w = fmaf(v1.w, nr1, acc2.w);
        }
        if (j < e2) {
            int r0 = g_csr_src[j];
            float nr0 = di * g_dinv[r0];
            float4 v0 = ((const float4*)(g_h + (size_t)r0 * HID))[lane];
            acc.x = fmaf(v0.x, nr0, acc.x);
            acc.y = fmaf(v0.y, nr0, acc.y);
            acc.z = fmaf(v0.z, nr0, acc.z);
            acc.w = fmaf(v0.w, nr0, acc.w);
        }
        acc.x += acc2.x; acc.y += acc2.y; acc.z += acc2.z; acc.w += acc2.w;
        ((float4*)(out + (size_t)node * HID))[lane] = acc;
    }

    *(float4*)&sh[wid][lane * 4]  = acc;
    *(float4*)&sh2[wid][lane * 4] = make_float4(acc.x * acc.x, acc.y * acc.y,
                                                acc.z * acc.z, acc.w * acc.w);
    __syncthreads();
    if (threadIdx.x < HID) {
        float s = 0.f, s2 = 0.f;
        #pragma unroll
        for (int w = 0; w < 8; w++) { s += sh[w][threadIdx.x]; s2 += sh2[w][threadIdx.x]; }
        atomicAdd(&g_sum[threadIdx.x],   s);
        atomicAdd(&g_sumsq[threadIdx.x], s2);
    }
}

// ---------------- K8: BN params recomputed per block + relu, in place ----------------
__global__ void k_bnrelu(float* __restrict__ out, int total4, int N,
                         const float* __restrict__ gamma, const float* __restrict__ beta) {
    __shared__ float s_scale[HID];
    __shared__ float s_shift[HID];
    if (threadIdx.x < HID) {
        int c = threadIdx.x;
        float invN = 1.0f / (float)N;
        float mean = g_sum[c] * invN;
        float var  = g_sumsq[c] * invN - mean * mean;
        float sc   = gamma[c] * rsqrtf(var + BN_EPS);
        s_scale[c] = sc;
        s_shift[c] = beta[c] - mean * sc;
    }
    __syncthreads();
    int i = blockIdx.x * blockDim.x + threadIdx.x;
    if (i >= total4) return;
    float4 v  = ((const float4*)out)[i];
    int ch4   = i & 31;
    float4 sc = *(const float4*)&s_scale[ch4 * 4];
    float4 sh = *(const float4*)&s_shift[ch4 * 4];
    v.x = fmaxf(fmaf(v.x, sc.x, sh.x), 0.f);
    v.y = fmaxf(fmaf(v.y, sc.y, sh.y), 0.f);
    v.z = fmaxf(fmaf(v.z, sc.z, sh.z), 0.f);
    v.w = fmaxf(fmaf(v.w, sc.w, sh.w), 0.f);
    ((float4*)out)[i] = v;
}

// ---------------- launch: fork-join; gemm at submission index 3 (ncu targeting) ----------------
extern "C" void kernel_launch(void* const* d_in, const int* in_sizes, int n_in,
                              void* d_out, int out_size) {
    const float* x     = (const float*)d_in[0];
    const int*   ei    = (const int*)d_in[1];     // int32 (JAX x64 disabled)
    const float* W     = (const float*)d_in[2];
    // d_in[3] = b : cancels inside BatchNorm, unused
    const float* gamma = (const float*)d_in[4];
    const float* beta  = (const float*)d_in[5];
    float*       out   = (float*)d_out;

    const int N = in_sizes[0] / INDIM;     // 50000
    const int E = in_sizes[1] / 2;         // 600000
    const int nblk = (N + SCAN_BLK - 1) / SCAN_BLK;

    static cudaStream_t s2 = nullptr;
    static cudaEvent_t evFork = nullptr, evJoin = nullptr;
    if (s2 == nullptr) {   // first (uncaptured correctness) call only: host-side setup
        cudaFuncSetAttribute(k_gemm_mma, cudaFuncAttributeMaxDynamicSharedMemorySize, SM_GEMM);
        cudaStreamCreateWithFlags(&s2, cudaStreamNonBlocking);
        cudaEventCreateWithFlags(&evFork, cudaEventDisableTiming);
        cudaEventCreateWithFlags(&evJoin, cudaEventDisableTiming);
    }

    cudaEventRecord(evFork, 0);
    cudaStreamWaitEvent(s2, evFork, 0);

    // submission order chosen so k_gemm_mma is launch index 3 (ncu captures idx 3)
    k_initS<<<1, HID>>>();                                     // idx 0 (main)
    k_wsplit<<<HID, 256>>>(W);                                 // idx 1 (main)
    k_initE<<<nblk, SCAN_BLK, 0, s2>>>(N);                     // idx 2 (side)
    k_gemm_mma<<<(N + 127) / 128, 256, SM_GEMM>>>(x, N);       // idx 3 (main)  <-- profiled

    k_deg<<<((E + 3) / 4 + 255) / 256, 256, 0, s2>>>(ei, E);   // side chain
    k_scan1<<<nblk, SCAN_BLK, 0, s2>>>(N);
    k_scan2<<<1, SCAN_BLK, 0, s2>>>(nblk);
    k_scan3<<<nblk, SCAN_BLK, 0, s2>>>(N);
    k_fill<<<((E + 3) / 4 + 255) / 256, 256, 0, s2>>>(ei, E);
    cudaEventRecord(evJoin, s2);

    cudaStreamWaitEvent(0, evJoin, 0);
    k_gather<<<(N + 7) / 8, 256>>>(out, N);
    k_bnrelu<<<(N * 32 + 255) / 256, 256>>>(out, N * 32, N, gamma, beta);
}

// round 11
// speedup vs baseline: 1.0925x; 1.0925x over previous
#include <cuda_runtime.h>
#include <cuda_bf16.h>
#include <cstdint>

#define NMAX 50000
#define EMAX 600000
#define HID 128
#define INDIM 256
#define BN_EPS 1e-5f
#define SCAN_BLK 256

// ---------------- scratch (no allocations allowed) ----------------
__device__ float g_h[(size_t)NMAX * HID];         // x @ W
__device__ __nv_bfloat16 g_wt_hi[HID * INDIM];    // W^T split hi: [n][k]
__device__ __nv_bfloat16 g_wt_lo[HID * INDIM];    // W^T split lo: [n][k]
__device__ int   g_degE[NMAX];
__device__ int   g_scan[NMAX];
__device__ int   g_rowptr[NMAX];
__device__ int   g_cursor[NMAX];
__device__ int   g_bsum[SCAN_BLK];
__device__ int   g_csr_src[EMAX];
__device__ float g_dinv[NMAX];
__device__ float g_sum[HID];
__device__ float g_sumsq[HID];

// ---------------- K0a (side stream): zero edge state ----------------
__global__ void k_initE(int N) {
    int i = blockIdx.x * blockDim.x + threadIdx.x;
    if (i < N) { g_degE[i] = 0; g_cursor[i] = 0; }
    if (i < SCAN_BLK) g_bsum[i] = 0;
}

// ---------------- K0b (main stream): zero BN stats ----------------
__global__ void k_initS() {
    g_sum[threadIdx.x] = 0.0f;
    g_sumsq[threadIdx.x] = 0.0f;
}

// ---------------- Kw: transpose + bf16-split W -> g_wt_hi/lo [n][k] ----------------
__global__ void k_wsplit(const float* __restrict__ W) {
    int n = blockIdx.x;
    for (int k = threadIdx.x; k < INDIM; k += blockDim.x) {
        float f = W[(size_t)k * HID + n];
        __nv_bfloat16 h = __float2bfloat16(f);
        float r = f - __bfloat162float(h);
        g_wt_hi[n * INDIM + k] = h;
        g_wt_lo[n * INDIM + k] = __float2bfloat16(r);
    }
}

// ================= K1: HMMA GEMM  h = x @ W  via bf16-split =================
// 512 threads, 16 warps, warp tile 32x32; single buffer, two syncs per chunk.
#define PITCH 72
#define PLANE (128 * PITCH * 2)          // bytes per plane = 18432
#define SA_HI 0
#define SA_LO (PLANE)
#define SB_HI (2 * PLANE)
#define SB_LO (3 * PLANE)
#define SM_GEMM (4 * PLANE)              // 73728 B

__device__ __forceinline__ void mma16816(float c[4], uint32_t a0, uint32_t a1,
                                         uint32_t a2, uint32_t a3,
                                         uint32_t b0, uint32_t b1) {
    asm volatile("mma.sync.aligned.m16n8k16.row.col.f32.bf16.bf16.f32 "
                 "{%0,%1,%2,%3},{%4,%5,%6,%7},{%8,%9},{%0,%1,%2,%3};"
                 : "+f"(c[0]), "+f"(c[1]), "+f"(c[2]), "+f"(c[3])
                 : "r"(a0), "r"(a1), "r"(a2), "r"(a3), "r"(b0), "r"(b1));
}

__global__ __launch_bounds__(512, 1)
void k_gemm_mma(const float* __restrict__ x, int M) {
    extern __shared__ char smem[];
    const int tid  = threadIdx.x;
    const int wid  = tid >> 5;      // 0..15
    const int lane = tid & 31;
    const int m0   = blockIdx.x * 128;

    const int wm = wid & 3;         // 4 M-subtiles of 32
    const int wn = wid >> 2;        // 4 N-subtiles of 32

    float c[2][4][4];
    #pragma unroll
    for (int mf = 0; mf < 2; mf++)
        #pragma unroll
        for (int nf = 0; nf < 4; nf++)
            #pragma unroll
            for (int qq = 0; qq < 4; qq++) c[mf][nf][qq] = 0.0f;

    const int srow = tid >> 2;          // 0..127 (loader row)
    const int q    = tid & 3;           // 16-col quarter of the 64-wide chunk
    const bool arow_ok = (m0 + srow) < M;

    const int groupID = lane >> 2;
    const int tq      = lane & 3;

    const float4* xsrc  = (const float4*)(x + (size_t)(m0 + srow) * INDIM + q * 16);
    const uint4*  whsrc = (const uint4*)(g_wt_hi + (size_t)srow * INDIM + q * 16);
    const uint4*  wlsrc = (const uint4*)(g_wt_lo + (size_t)srow * INDIM + q * 16);

    float4 fx[4];
    uint4  bh[2], bl[2];

    #pragma unroll
    for (int v = 0; v < 4; v++)
        fx[v] = arow_ok ? xsrc[v] : make_float4(0.f, 0.f, 0.f, 0.f);
    #pragma unroll
    for (int v = 0; v < 2; v++) { bh[v] = whsrc[v]; bl[v] = wlsrc[v]; }

    #pragma unroll 1
    for (int ch = 0; ch < INDIM / 64; ch++) {
        {
            char* ahi = smem + SA_HI + (size_t)srow * PITCH * 2 + q * 32;
            char* alo = smem + SA_LO + (size_t)srow * PITCH * 2 + q * 32;
            #pragma unroll
            for (int v = 0; v < 4; v++) {
                float4 f = fx[v];
                __nv_bfloat16 hx = __float2bfloat16(f.x), hy = __float2bfloat16(f.y);
                __nv_bfloat16 hz = __float2bfloat16(f.z), hw = __float2bfloat16(f.w);
                __nv_bfloat162 h01 = {hx, hy}, h23 = {hz, hw};
                __nv_bfloat162 l01 = {__float2bfloat16(f.x - __bfloat162float(hx)),
                                      __float2bfloat16(f.y - __bfloat162float(hy))};
                __nv_bfloat162 l23 = {__float2bfloat16(f.z - __bfloat162float(hz)),
                                      __float2bfloat16(f.w - __bfloat162float(hw))};
                *(uint32_t*)(ahi + v * 8)     = *(uint32_t*)&h01;
                *(uint32_t*)(ahi + v * 8 + 4) = *(uint32_t*)&h23;
                *(uint32_t*)(alo + v * 8)     = *(uint32_t*)&l01;
                *(uint32_t*)(alo + v * 8 + 4) = *(uint32_t*)&l23;
            }
            char* bhi = smem + SB_HI + (size_t)srow * PITCH * 2 + q * 32;
            char* blo = smem + SB_LO + (size_t)srow * PITCH * 2 + q * 32;
            #pragma unroll
            for (int v = 0; v < 2; v++) {
                *(uint4*)(bhi + v * 16) = bh[v];
                *(uint4*)(blo + v * 16) = bl[v];
            }
        }
        __syncthreads();

        if (ch < INDIM / 64 - 1) {
            #pragma unroll
            for (int v = 0; v < 4; v++)
                fx[v] = arow_ok ? xsrc[(ch + 1) * 16 + v] : make_float4(0.f, 0.f, 0.f, 0.f);
            #pragma unroll
            for (int v = 0; v < 2; v++) {
                bh[v] = whsrc[(ch + 1) * 8 + v];
                bl[v] = wlsrc[(ch + 1) * 8 + v];
            }
        }

        #pragma unroll
        for (int ks = 0; ks < 4; ks++) {
            const int kk = ks * 16 + 2 * tq;
            uint32_t ahi[2][4], alo[2][4];
            #pragma unroll
            for (int mf = 0; mf < 2; mf++) {
                int r0 = wm * 32 + mf * 16 + groupID;
                const char* ph = smem + SA_HI;
                const char* pl = smem + SA_LO;
                ahi[mf][0] = *(const uint32_t*)(ph + ((size_t)r0 * PITCH + kk) * 2);
                ahi[mf][1] = *(const uint32_t*)(ph + ((size_t)(r0 + 8) * PITCH + kk) * 2);
                ahi[mf][2] = *(const uint32_t*)(ph + ((size_t)r0 * PITCH + kk + 8) * 2);
                ahi[mf][3] = *(const uint32_t*)(ph + ((size_t)(r0 + 8) * PITCH + kk + 8) * 2);
                alo[mf][0] = *(const uint32_t*)(pl + ((size_t)r0 * PITCH + kk) * 2);
                alo[mf][1] = *(const uint32_t*)(pl + ((size_t)(r0 + 8) * PITCH + kk) * 2);
                alo[mf][2] = *(const uint32_t*)(pl + ((size_t)r0 * PITCH + kk + 8) * 2);
                alo[mf][3] = *(const uint32_t*)(pl + ((size_t)(r0 + 8) * PITCH + kk + 8) * 2);
            }
            #pragma unroll
            for (int nf = 0; nf < 4; nf++) {
                int nr = wn * 32 + nf * 8 + groupID;
                uint32_t bh0 = *(const uint32_t*)(smem + SB_HI + ((size_t)nr * PITCH + kk) * 2);
                uint32_t bh1 = *(const uint32_t*)(smem + SB_HI + ((size_t)nr * PITCH + kk + 8) * 2);
                uint32_t bl0 = *(const uint32_t*)(smem + SB_LO + ((size_t)nr * PITCH + kk) * 2);
                uint32_t bl1 = *(const uint32_t*)(smem + SB_LO + ((size_t)nr * PITCH + kk + 8) * 2);
                #pragma unroll
                for (int mf = 0; mf < 2; mf++) {
                    mma16816(c[mf][nf], ahi[mf][0], ahi[mf][1], ahi[mf][2], ahi[mf][3], bh0, bh1);
                    mma16816(c[mf][nf], ahi[mf][0], ahi[mf][1], ahi[mf][2], ahi[mf][3], bl0, bl1);
                    mma16816(c[mf][nf], alo[mf][0], alo[mf][1], alo[mf][2], alo[mf][3], bh0, bh1);
                }
            }
        }
        if (ch < INDIM / 64 - 1) __syncthreads();
    }

    #pragma unroll
    for (int mf = 0; mf < 2; mf++) {
        int r0 = m0 + wm * 32 + mf * 16 + groupID;
        #pragma unroll
        for (int nf = 0; nf < 4; nf++) {
            int n0 = wn * 32 + nf * 8 + 2 * tq;
            if (r0 < M)
                *(float2*)(g_h + (size_t)r0 * HID + n0) = make_float2(c[mf][nf][0], c[mf][nf][1]);
            if (r0 + 8 < M)
                *(float2*)(g_h + (size_t)(r0 + 8) * HID + n0) = make_float2(c[mf][nf][2], c[mf][nf][3]);
        }
    }
}

// ---------------- K2: in-degree on targets (4 edges/thread, int4) ----------------
__global__ void k_deg(const int* __restrict__ ei, int E) {
    int t = blockIdx.x * blockDim.x + threadIdx.x;
    int e4 = t * 4;
    if (e4 + 3 < E) {
        int4 cc = *(const int4*)(ei + E + e4);
        atomicAdd(&g_degE[cc.x], 1);
        atomicAdd(&g_degE[cc.y], 1);
        atomicAdd(&g_degE[cc.z], 1);
        atomicAdd(&g_degE[cc.w], 1);
    } else {
        for (int e = e4; e < E; e++) atomicAdd(&g_degE[ei[E + e]], 1);
    }
}

// ---------------- warp-shuffle inclusive scan helpers ----------------
__device__ __forceinline__ int warp_iscan(int v, int lane) {
    #pragma unroll
    for (int off = 1; off < 32; off <<= 1) {
        int t = __shfl_up_sync(0xFFFFFFFF, v, off);
        if (lane >= off) v += t;
    }
    return v;
}

__global__ void k_scan1(int N) {
    __shared__ int wsum[8];
    int i = blockIdx.x * SCAN_BLK + threadIdx.x;
    int lane = threadIdx.x & 31, wid = threadIdx.x >> 5;
    int v = (i < N) ? g_degE[i] : 0;
    v = warp_iscan(v, lane);
    if (lane == 31) wsum[wid] = v;
    __syncthreads();
    if (wid == 0) {
        int s = (lane < 8) ? wsum[lane] : 0;
        s = warp_iscan(s, lane);
        if (lane < 8) wsum[lane] = s;
    }
    __syncthreads();
    if (wid > 0) v += wsum[wid - 1];
    if (i < N) g_scan[i] = v;
    if (threadIdx.x == SCAN_BLK - 1) g_bsum[blockIdx.x] = v;
}

__global__ void k_scan2(int nblk) {
    __shared__ int wsum[8];
    int lane = threadIdx.x & 31, wid = threadIdx.x >> 5;
    int v = (threadIdx.x < nblk) ? g_bsum[threadIdx.x] : 0;
    v = warp_iscan(v, lane);
    if (lane == 31) wsum[wid] = v;
    __syncthreads();
    if (wid == 0) {
        int s = (lane < 8) ? wsum[lane] : 0;
        s = warp_iscan(s, lane);
        if (lane < 8) wsum[lane] = s;
    }
    __syncthreads();
    if (wid > 0) v += wsum[wid - 1];
    g_bsum[threadIdx.x] = v;
}

__global__ void k_scan3(int N) {
    int i = blockIdx.x * SCAN_BLK + threadIdx.x;
    if (i >= N) return;
    int base = (blockIdx.x > 0) ? g_bsum[blockIdx.x - 1] : 0;
    g_rowptr[i] = base + g_scan[i] - g_degE[i];
    g_dinv[i]   = rsqrtf((float)(g_degE[i] + 1));
}

// ---------------- K4: fill CSR source list (4 edges/thread) ----------------
__global__ void k_fill(const int* __restrict__ ei, int E) {
    int t = blockIdx.x * blockDim.x + threadIdx.x;
    int e4 = t * 4;
    if (e4 + 3 < E) {
        int4 rr = *(const int4*)(ei + e4);
        int4 cc = *(const int4*)(ei + E + e4);
        int p;
        p = atomicAdd(&g_cursor[cc.x], 1); g_csr_src[g_rowptr[cc.x] + p] = rr.x;
        p = atomicAdd(&g_cursor[cc.y], 1); g_csr_src[g_rowptr[cc.y] + p] = rr.y;
        p = atomicAdd(&g_cursor[cc.z], 1); g_csr_src[g_rowptr[cc.z] + p] = rr.z;
        p = atomicAdd(&g_cursor[cc.w], 1); g_csr_src[g_rowptr[cc.w] + p] = rr.w;
    } else {
        for (int e = e4; e < E; e++) {
            int r = ei[e], c = ei[E + e];
            int p = atomicAdd(&g_cursor[c], 1);
            g_csr_src[g_rowptr[c] + p] = r;
        }
    }
}

// ---------------- K5: gather-reduce + fused BN stats (2-way unrolled) ----------------
__global__ void k_gather(float* __restrict__ out, int N) {
    __shared__ float sh[8][HID];
    __shared__ float sh2[8][HID];
    const int wid  = threadIdx.x >> 5;
    const int lane = threadIdx.x & 31;
    const int node = blockIdx.x * 8 + wid;

    float4 acc = make_float4(0.f, 0.f, 0.f, 0.f);
    if (node < N) {
        float di = g_dinv[node];
        acc = ((const float4*)(g_h + (size_t)node * HID))[lane];
        float n2 = di * di;
        acc.x *= n2; acc.y *= n2; acc.z *= n2; acc.w *= n2;

        int s  = g_rowptr[node];
        int e2 = s + g_degE[node];
        float4 acc2 = make_float4(0.f, 0.f, 0.f, 0.f);
        int j = s;
        for (; j + 1 < e2; j += 2) {
            int r0 = g_csr_src[j];
            int r1 = g_csr_src[j + 1];
            float nr0 = di * g_dinv[r0];
            float nr1 = di * g_dinv[r1];
            float4 v0 = ((const float4*)(g_h + (size_t)r0 * HID))[lane];
            float4 v1 = ((const float4*)(g_h + (size_t)r1 * HID))[lane];
            acc.x  = fmaf(v0.x, nr0, acc.x);
            acc.y  = fmaf(v0.y, nr0, acc.y);
            acc.z  = fmaf(v0.z, nr0, acc.z);
            acc.w  = fmaf(v0.w, nr0, acc.w);
            acc2.x = fmaf(v1.x, nr1, acc2.x);
            acc2.y = fmaf(v1.y, nr1, acc2.y);
            acc2.z = fmaf(v1.z, nr1, acc2.z);
            acc2.w = fmaf(v1.w, nr1, acc2.w);
        }
        if (j < e2) {
            int r0 = g_csr_src[j];
            float nr0 = di * g_dinv[r0];
            float4 v0 = ((const float4*)(g_h + (size_t)r0 * HID))[lane];
            acc.x = fmaf(v0.x, nr0, acc.x);
            acc.y = fmaf(v0.y, nr0, acc.y);
            acc.z = fmaf(v0.z, nr0, acc.z);
            acc.w = fmaf(v0.w, nr0, acc.w);
        }
        acc.x += acc2.x; acc.y += acc2.y; acc.z += acc2.z; acc.w += acc2.w;
        ((float4*)(out + (size_t)node * HID))[lane] = acc;
    }

    *(float4*)&sh[wid][lane * 4]  = acc;
    *(float4*)&sh2[wid][lane * 4] = make_float4(acc.x * acc.x, acc.y * acc.y,
                                                acc.z * acc.z, acc.w * acc.w);
    __syncthreads();
    if (threadIdx.x < HID) {
        float s = 0.f, s2 = 0.f;
        #pragma unroll
        for (int w = 0; w < 8; w++) { s += sh[w][threadIdx.x]; s2 += sh2[w][threadIdx.x]; }
        atomicAdd(&g_sum[threadIdx.x],   s);
        atomicAdd(&g_sumsq[threadIdx.x], s2);
    }
}

// ---------------- K8: BN params recomputed per block + relu, in place ----------------
__global__ void k_bnrelu(float* __restrict__ out, int total4, int N,
                         const float* __restrict__ gamma, const float* __restrict__ beta) {
    __shared__ float s_scale[HID];
    __shared__ float s_shift[HID];
    if (threadIdx.x < HID) {
        int c = threadIdx.x;
        float invN = 1.0f / (float)N;
        float mean = g_sum[c] * invN;
        float var  = g_sumsq[c] * invN - mean * mean;
        float sc   = gamma[c] * rsqrtf(var + BN_EPS);
        s_scale[c] = sc;
        s_shift[c] = beta[c] - mean * sc;
    }
    __syncthreads();
    int i = blockIdx.x * blockDim.x + threadIdx.x;
    if (i >= total4) return;
    float4 v  = ((const float4*)out)[i];
    int ch4   = i & 31;
    float4 sc = *(const float4*)&s_scale[ch4 * 4];
    float4 sh = *(const float4*)&s_shift[ch4 * 4];
    v.x = fmaxf(fmaf(v.x, sc.x, sh.x), 0.f);
    v.y = fmaxf(fmaf(v.y, sc.y, sh.y), 0.f);
    v.z = fmaxf(fmaf(v.z, sc.z, sh.z), 0.f);
    v.w = fmaxf(fmaf(v.w, sc.w, sh.w), 0.f);
    ((float4*)out)[i] = v;
}

// ---------------- launch: fork-join; gemm at submission index 3 (ncu targeting) ----------------
extern "C" void kernel_launch(void* const* d_in, const int* in_sizes, int n_in,
                              void* d_out, int out_size) {
    const float* x     = (const float*)d_in[0];
    const int*   ei    = (const int*)d_in[1];     // int32 (JAX x64 disabled)
    const float* W     = (const float*)d_in[2];
    // d_in[3] = b : cancels inside BatchNorm, unused
    const float* gamma = (const float*)d_in[4];
    const float* beta  = (const float*)d_in[5];
    float*       out   = (float*)d_out;

    const int N = in_sizes[0] / INDIM;     // 50000
    const int E = in_sizes[1] / 2;         // 600000
    const int nblk = (N + SCAN_BLK - 1) / SCAN_BLK;

    static cudaStream_t s2 = nullptr;
    static cudaEvent_t evFork = nullptr, evJoin = nullptr;
    if (s2 == nullptr) {   // first (uncaptured correctness) call only: host-side setup
        cudaFuncSetAttribute(k_gemm_mma, cudaFuncAttributeMaxDynamicSharedMemorySize, SM_GEMM);
        cudaStreamCreateWithFlags(&s2, cudaStreamNonBlocking);
        cudaEventCreateWithFlags(&evFork, cudaEventDisableTiming);
        cudaEventCreateWithFlags(&evJoin, cudaEventDisableTiming);
    }

    cudaEventRecord(evFork, 0);
    cudaStreamWaitEvent(s2, evFork, 0);

    // submission order chosen so k_gemm_mma is launch index 3 (ncu captures idx 3)
    k_initS<<<1, HID>>>();                                     // idx 0 (main)
    k_wsplit<<<HID, 256>>>(W);                                 // idx 1 (main)
    k_initE<<<nblk, SCAN_BLK, 0, s2>>>(N);                     // idx 2 (side)
    k_gemm_mma<<<(N + 127) / 128, 512, SM_GEMM>>>(x, N);       // idx 3 (main)  <-- profiled

    k_deg<<<((E + 3) / 4 + 255) / 256, 256, 0, s2>>>(ei, E);   // side chain
    k_scan1<<<nblk, SCAN_BLK, 0, s2>>>(N);
    k_scan2<<<1, SCAN_BLK, 0, s2>>>(nblk);
    k_scan3<<<nblk, SCAN_BLK, 0, s2>>>(N);
    k_fill<<<((E + 3) / 4 + 255) / 256, 256, 0, s2>>>(ei, E);
    cudaEventRecord(evJoin, s2);

    cudaStreamWaitEvent(0, evJoin, 0);
    k_gather<<<(N + 7) / 8, 256>>>(out, N);
    k_bnrelu<<<(N * 32 + 255) / 256, 256>>>(out, N * 32, N, gamma, beta);
}